// round 2
// baseline (speedup 1.0000x reference)
#include <cuda_runtime.h>
#include <cstdint>

// ---------------- problem constants ----------------
#define D_   256
#define V_   8192
#define B_   64
#define T_   16
#define L_   1024          // B*T
#define C_   64            // C_STD
#define N_   1024          // T*C_STD
#define ZQ_SIZE  (B_*N_*D_)            // 16777216
#define OFF_LOSS (ZQ_SIZE)             // 16777216
#define OFF_IDX  (ZQ_SIZE+1)           // 16777217
#define NIDX     (L_*85)               // 87040
#define OFF_CS   (OFF_IDX + NIDX)      // 16864257
#define MAXM     (L_*64)               // 65536

typedef unsigned long long ull;

// ---------------- device scratch (static globals; no cudaMalloc allowed) ----
__device__ float g_en[V_*D_];          // normalized embedding       (8 MB)
__device__ float g_Bt[D_*768];         // transposed phi_w           (0.75 MB)
__device__ float g_E[V_*768];          // E_k[v,o] = sum_i w[o,i,k]*en[v,i]  (24 MB)
__device__ float g_zl[L_*C_*D_];       // z_LND                      (64 MB)
__device__ float g_fhat[L_*C_*D_];     // running f_hat              (64 MB)
__device__ float g_q[MAXM*D_];         // normalized block means     (64 MB)
__device__ ull   g_keys[MAXM];
__device__ int   g_idxcur[MAXM];
__device__ float g_counts[V_];
__device__ double g_loss;

// ---------------- helpers ----------------
__device__ __forceinline__ float blockReduceSum(float v) {
    __shared__ float sh[8];
    int lane = threadIdx.x & 31, w = threadIdx.x >> 5;
    #pragma unroll
    for (int o = 16; o; o >>= 1) v += __shfl_down_sync(0xffffffffu, v, o);
    if (lane == 0) sh[w] = v;
    __syncthreads();
    if (w == 0) {
        v = (lane < 8) ? sh[lane] : 0.f;
        #pragma unroll
        for (int o = 4; o; o >>= 1) v += __shfl_down_sync(0xffffffffu, v, o);
        if (lane == 0) sh[0] = v;
    }
    __syncthreads();
    return sh[0];
}

__device__ __forceinline__ unsigned order_f(float f) {
    unsigned u = __float_as_uint(f);
    return (u & 0x80000000u) ? ~u : (u | 0x80000000u);
}

// packed f32x2 FMA (sm_100+): 2x fp32 rate vs FFMA-3reg
__device__ __forceinline__ void fma2(ull &acc, ull a, ull b) {
    asm("fma.rn.f32x2 %0, %1, %2, %0;" : "+l"(acc) : "l"(a), "l"(b));
}
__device__ __forceinline__ ull dup2(float a) {
    ull r; unsigned u = __float_as_uint(a);
    asm("mov.b64 %0, {%1, %1};" : "=l"(r) : "r"(u));
    return r;
}
__device__ __forceinline__ void unpack2(ull p, float &lo, float &hi) {
    unsigned a, b;
    asm("mov.b64 {%0, %1}, %2;" : "=r"(a), "=r"(b) : "l"(p));
    lo = __uint_as_float(a); hi = __uint_as_float(b);
}

// ---------------- init / prep kernels ----------------
__global__ void k_zero() {
    int i = blockIdx.x * 256 + threadIdx.x;      // grid 65536x256 = 16.7M
    g_fhat[i] = 0.f;
    if (i < V_) g_counts[i] = 0.f;
    if (i == 0) g_loss = 0.0;
}

__global__ void k_norm_embed(const float* __restrict__ emb) {
    int v = blockIdx.x, d = threadIdx.x;
    float x = emb[v*D_ + d];
    float ss = blockReduceSum(x*x);
    float inv = 1.0f / fmaxf(sqrtf(ss), 1e-12f);
    g_en[v*D_ + d] = x * inv;
}

__global__ void k_transpose_w(const float* __restrict__ w) {
    int e = blockIdx.x * 256 + threadIdx.x;      // 768 blocks -> 196608
    int o = e / 768, rem = e % 768;
    int i = rem / 3, k = rem % 3;
    g_Bt[i*768 + o*3 + k] = w[e];
}

// E = en(8192x256) @ Bt(256x768), plain fp32 tiled GEMM (cost ~3.2 GFLOP)
__global__ __launch_bounds__(256) void k_gemm_E() {
    __shared__ float As[32][68];
    __shared__ float Bs[32][68];
    int tid = threadIdx.x, tx = tid & 15, ty = tid >> 4;
    int rb = blockIdx.x * 64, cb = blockIdx.y * 64;
    float acc[4][4];
    #pragma unroll
    for (int i = 0; i < 4; i++)
        #pragma unroll
        for (int j = 0; j < 4; j++) acc[i][j] = 0.f;

    for (int kt = 0; kt < D_/32; kt++) {
        #pragma unroll
        for (int i = 0; i < 2; i++) {            // A: 64x32 = 512 f4
            int f4 = tid + i*256;
            int r = f4 >> 3, kq = (f4 & 7) * 4;
            float4 v = *(const float4*)&g_en[(rb + r)*D_ + kt*32 + kq];
            As[kq+0][r] = v.x; As[kq+1][r] = v.y; As[kq+2][r] = v.z; As[kq+3][r] = v.w;
        }
        #pragma unroll
        for (int i = 0; i < 2; i++) {            // B: 32x64 = 512 f4
            int f4 = tid + i*256;
            int r = f4 >> 4, cq = (f4 & 15) * 4;
            float4 v = *(const float4*)&g_Bt[(kt*32 + r)*768 + cb + cq];
            *(float4*)&Bs[r][cq] = v;
        }
        __syncthreads();
        #pragma unroll
        for (int kk = 0; kk < 32; kk++) {
            float4 a = *(const float4*)&As[kk][ty*4];
            float4 b = *(const float4*)&Bs[kk][tx*4];
            float ar[4] = {a.x, a.y, a.z, a.w};
            float br[4] = {b.x, b.y, b.z, b.w};
            #pragma unroll
            for (int i = 0; i < 4; i++)
                #pragma unroll
                for (int j = 0; j < 4; j++) acc[i][j] += ar[i] * br[j];
        }
        __syncthreads();
    }
    #pragma unroll
    for (int i = 0; i < 4; i++)
        #pragma unroll
        for (int j = 0; j < 4; j++)
            g_E[(rb + ty*4 + i)*768 + cb + tx*4 + j] = acc[i][j];
}

// normalize z rows and scatter by channel permutation -> g_zl
__global__ void k_scatter_z(const float* __restrict__ z, const int* __restrict__ chans) {
    int row = blockIdx.x;                        // b*N + n, grid 65536
    int d = threadIdx.x;
    int b = row >> 10, n = row & 1023;
    float x = z[row*D_ + d];
    float ss = blockReduceSum(x*x);
    float inv = 1.0f / fmaxf(sqrtf(ss), 1e-12f);
    int csrc = n & 63, t = n >> 6;
    int ch = chans[b*N_ + csrc];
    int l = (b << 4) + t;
    g_zl[((l << 6) + ch)*D_ + d] = x * inv;
}

// ---------------- per-round kernels ----------------
// block means of (zl - fhat), normalized -> g_q ; also resets g_keys
__global__ void k_means(int g) {
    int row = blockIdx.x;                        // row = l*g + j, grid = L*g
    int d = threadIdx.x;
    int l = row / g, j = row % g;
    int s = C_ / g;
    int base = (l*C_ + j*s)*D_ + d;
    float sum = 0.f;
    for (int c = 0; c < s; c++) sum += g_zl[base + c*D_] - g_fhat[base + c*D_];
    sum *= (1.0f / s);
    float ss = blockReduceSum(sum*sum);
    float inv = 1.0f / fmaxf(sqrtf(ss), 1e-12f);
    if (d == 0) g_keys[row] = 0ULL;
    g_q[row*D_ + d] = sum * inv;
}

// fused fp32 GEMM (q @ en^T) + argmax epilogue, FFMA2 inner loop.
// BM=128 rows, V chunk=512, BN=64, BK=32, 256 thr (16x16), TM=8, TN=4(2 pairs)
#define GA_BM 128
#define GA_BN 64
#define GA_BK 32
#define GA_VC 512
__global__ __launch_bounds__(256, 2) void k_gemm_argmax(int M) {
    __shared__ float As[GA_BK][GA_BM + 4];
    __shared__ float Bs[GA_BK][GA_BN + 4];
    __shared__ float s_val[GA_BM][16];
    __shared__ int   s_idx[GA_BM][16];

    int tid = threadIdx.x, tx = tid & 15, ty = tid >> 4;
    int rowbase = blockIdx.x * GA_BM;
    int vbase = blockIdx.y * GA_VC;

    float bestv[8]; int bestid[8];
    #pragma unroll
    for (int i = 0; i < 8; i++) { bestv[i] = -1e30f; bestid[i] = 0; }

    for (int nt = 0; nt < GA_VC/GA_BN; nt++) {
        int cb = vbase + nt*GA_BN;
        ull acc[8][2];
        #pragma unroll
        for (int i = 0; i < 8; i++) { acc[i][0] = 0ULL; acc[i][1] = 0ULL; }

        for (int kt = 0; kt < D_/GA_BK; kt++) {
            #pragma unroll
            for (int i = 0; i < 4; i++) {        // A: 128x32 = 1024 f4
                int f4 = tid + i*256;
                int r = f4 >> 3, kq = (f4 & 7) * 4;
                float4 v = *(const float4*)&g_q[(rowbase + r)*D_ + kt*GA_BK + kq];
                As[kq+0][r] = v.x; As[kq+1][r] = v.y; As[kq+2][r] = v.z; As[kq+3][r] = v.w;
            }
            #pragma unroll
            for (int i = 0; i < 2; i++) {        // B: 64x32 = 512 f4
                int f4 = tid + i*256;
                int r = f4 >> 3, kq = (f4 & 7) * 4;
                float4 v = *(const float4*)&g_en[(cb + r)*D_ + kt*GA_BK + kq];
                Bs[kq+0][r] = v.x; Bs[kq+1][r] = v.y; Bs[kq+2][r] = v.z; Bs[kq+3][r] = v.w;
            }
            __syncthreads();
            #pragma unroll
            for (int kk = 0; kk < GA_BK; kk++) {
                float4 a0 = *(const float4*)&As[kk][ty*8];
                float4 a1 = *(const float4*)&As[kk][ty*8 + 4];
                ull b0 = *(const ull*)&Bs[kk][tx*4];
                ull b1 = *(const ull*)&Bs[kk][tx*4 + 2];
                float ar[8] = {a0.x, a0.y, a0.z, a0.w, a1.x, a1.y, a1.z, a1.w};
                #pragma unroll
                for (int i = 0; i < 8; i++) {
                    ull ad = dup2(ar[i]);
                    fma2(acc[i][0], ad, b0);
                    fma2(acc[i][1], ad, b1);
                }
            }
            __syncthreads();
        }
        // fold this 64-wide tile into running argmax (ascending col order)
        #pragma unroll
        for (int i = 0; i < 8; i++) {
            #pragma unroll
            for (int p = 0; p < 2; p++) {
                float lo, hi;
                unpack2(acc[i][p], lo, hi);
                int c = cb + tx*4 + p*2;
                if (lo > bestv[i]) { bestv[i] = lo; bestid[i] = c; }
                if (hi > bestv[i]) { bestv[i] = hi; bestid[i] = c + 1; }
            }
        }
    }
    // cross-thread (tx) reduction per row, tie -> smaller idx
    #pragma unroll
    for (int i = 0; i < 8; i++) { s_val[ty*8 + i][tx] = bestv[i]; s_idx[ty*8 + i][tx] = bestid[i]; }
    __syncthreads();
    if (tid < GA_BM) {
        float bv = s_val[tid][0]; int bi = s_idx[tid][0];
        #pragma unroll
        for (int j = 1; j < 16; j++) {
            float v = s_val[tid][j]; int ii = s_idx[tid][j];
            if (v > bv || (v == bv && ii < bi)) { bv = v; bi = ii; }
        }
        ull key = ((ull)order_f(bv) << 32) | (ull)(0xFFFFFFFFu - (unsigned)bi);
        atomicMax(&g_keys[rowbase + tid], key);
    }
}

__global__ void k_finalize(int g, int colbase, int M, float* __restrict__ out) {
    int row = blockIdx.x * 256 + threadIdx.x;
    if (row >= M) return;
    ull key = g_keys[row];
    int idx = (int)(0xFFFFFFFFu - (unsigned)(key & 0xFFFFFFFFu));
    g_idxcur[row] = idx;
    int l = row / g, j = row % g;
    out[OFF_IDX + l*85 + colbase + j] = (float)idx;
    atomicAdd(&g_counts[idx], 1.0f);
}

// gather-based phi_apply, update f_hat, accumulate loss sumsq
__global__ void k_assemble(int g, const float* __restrict__ phib) {
    int l = blockIdx.x, d = threadIdx.x;
    int s = C_ / g;
    __shared__ int sidx[64];
    if (d < g) sidx[d] = g_idxcur[l*g + d];
    __syncthreads();
    float bb = phib[d];
    float lsum = 0.f;
    for (int c = 0; c < C_; c++) {
        int vb = sidx[c / s];
        float y = g_E[vb*768 + d*3 + 1] + bb;
        if (c > 0)      y += g_E[sidx[(c-1)/s]*768 + d*3 + 0];
        if (c < C_-1)   y += g_E[sidx[(c+1)/s]*768 + d*3 + 2];
        float h = 0.5f*g_en[vb*D_ + d] + 0.5f*y;
        int off = (l*C_ + c)*D_ + d;
        float f = g_fhat[off] + h;
        g_fhat[off] = f;
        float diff = f - g_zl[off];
        lsum += diff * diff;
    }
    float tot = blockReduceSum(lsum);
    if (d == 0) atomicAdd(&g_loss, (double)tot);
}

// ---------------- epilogue kernels ----------------
__global__ void k_gather_zq(const int* __restrict__ chans, float* __restrict__ out) {
    int row = blockIdx.x;                        // b*N + n
    int d = threadIdx.x;
    int b = row >> 10, n = row & 1023;
    int csrc = n & 63, t = n >> 6;
    int ch = chans[b*N_ + csrc];
    int l = (b << 4) + t;
    out[row*D_ + d] = g_fhat[((l << 6) + ch)*D_ + d];
}

__global__ void k_tail(const float* __restrict__ cs, float* __restrict__ out) {
    int v = blockIdx.x * 256 + threadIdx.x;
    out[OFF_CS + v] = 0.99f * cs[v] + 0.01f * g_counts[v];
    if (v == 0)
        out[OFF_LOSS] = (float)(g_loss * (1.25 / (4.0 * (double)(L_*C_*D_))));
}

// ---------------- launch ----------------
extern "C" void kernel_launch(void* const* d_in, const int* in_sizes, int n_in,
                              void* d_out, int out_size) {
    const float* z     = (const float*)d_in[0];
    const int*   chans = (const int*)d_in[1];
    // d_in[2] = input_time (unused by reference)
    const float* emb   = (const float*)d_in[3];
    const float* w     = (const float*)d_in[4];
    const float* phib  = (const float*)d_in[5];
    const float* cs    = (const float*)d_in[6];
    float* out = (float*)d_out;

    k_zero<<<65536, 256>>>();
    k_norm_embed<<<V_, 256>>>(emb);
    k_transpose_w<<<768, 256>>>(w);
    k_gemm_E<<<dim3(V_/64, 12), 256>>>();
    k_scatter_z<<<B_*N_, 256>>>(z, chans);

    const int gs[4]      = {1, 4, 16, 64};
    const int colbase[4] = {0, 1, 5, 21};
    for (int r = 0; r < 4; r++) {
        int g = gs[r];
        int M = L_ * g;
        k_means<<<M, 256>>>(g);
        k_gemm_argmax<<<dim3(M/GA_BM, V_/GA_VC), 256>>>(M);
        k_finalize<<<(M + 255)/256, 256>>>(g, colbase[r], M, out);
        k_assemble<<<L_, 256>>>(g, phib);
    }

    k_gather_zq<<<B_*N_, 256>>>(chans, out);
    k_tail<<<V_/256, 256>>>(cs, out);
}